// round 15
// baseline (speedup 1.0000x reference)
#include <cuda_runtime.h>
#include <cuda_bf16.h>
#include <cuda_fp16.h>
#include <math.h>
#include <stdint.h>

#define NMAX 4096
#define KMAX 512
#define LTMAX 1024   // >= 32*33/2 = 528 triangular tiles (gemm)

// ---- scratch (__device__ globals; allocation-free rule) ----
__device__ __half         d_hbuf[(size_t)NMAX * NMAX];  // distances, fp16
__device__ __nv_bfloat16  g_xb[(size_t)NMAX * KMAX];
__device__ float          g_sqn[NMAX];
__device__ float          g_partials[LTMAX];

// ===========================================================================
// helpers (generic PTX only: ldmatrix / mma.sync bf16 / cp.async)
// ===========================================================================
__device__ __forceinline__ uint32_t smem_u32(const void* p) {
    uint32_t a;
    asm("{ .reg .u64 t; cvta.to.shared.u64 t, %1; cvt.u32.u64 %0, t; }"
        : "=r"(a) : "l"(p));
    return a;
}

#define CP_ASYNC16(saddr, gptr) \
    asm volatile("cp.async.cg.shared.global [%0], [%1], 16;" \
                 :: "r"(saddr), "l"((const void*)(gptr)) : "memory")
#define CP_COMMIT()  asm volatile("cp.async.commit_group;" ::: "memory")
#define CP_WAIT(n)   asm volatile("cp.async.wait_group %0;" :: "n"(n) : "memory")

#define LDSM_X4(r0, r1, r2, r3, addr) \
    asm volatile("ldmatrix.sync.aligned.m8n8.x4.shared.b16 {%0,%1,%2,%3}, [%4];" \
                 : "=r"(r0), "=r"(r1), "=r"(r2), "=r"(r3) : "r"(addr))

#define MMA_BF16(c, a, b) \
    asm volatile("mma.sync.aligned.m16n8k16.row.col.f32.bf16.bf16.f32 " \
                 "{%0,%1,%2,%3}, {%4,%5,%6,%7}, {%8,%9}, {%0,%1,%2,%3};" \
                 : "+f"((c)[0]), "+f"((c)[1]), "+f"((c)[2]), "+f"((c)[3]) \
                 : "r"((a)[0]), "r"((a)[1]), "r"((a)[2]), "r"((a)[3]), \
                   "r"((b)[0]), "r"((b)[1]))

// FMA/ALU-only exp2: magic-number range reduction (NO FRND, NO F2I —
// conversion-class ops are quarter-rate). x <= 0 expected; clamped at -60.
__device__ __forceinline__ float fexp2(float x) {
    x = fmaxf(x, -60.f);
    const float MAGIC = 12582912.f;            // 2^23 * 1.5
    float y = __fadd_rn(x, MAGIC);             // RN -> nearest int in mantissa
    int   ni = __float_as_int(y) - 0x4B400000; // linear mantissa -> n
    float f = __fadd_rn(x, -__fadd_rn(y, -MAGIC));   // f = x - n, [-0.5, 0.5]
    float p = 1.33336e-3f;
    p = fmaf(p, f, 9.61813e-3f);
    p = fmaf(p, f, 5.550411e-2f);
    p = fmaf(p, f, 2.4022651e-1f);
    p = fmaf(p, f, 6.9314718e-1f);
    p = fmaf(p, f, 1.0f);
    return __int_as_float((ni + 127) << 23) * p;
}

// ===========================================================================
// Kernel 0: fused fp32 -> bf16 convert + row squared norms (warp per row,
// 4 unrolled float4 loads -> MLP=4/thread).
// ===========================================================================
__global__ void __launch_bounds__(256) prep_kernel(const float* __restrict__ x, int K) {
    int w    = threadIdx.x >> 5;
    int lane = threadIdx.x & 31;
    int row  = blockIdx.x * 8 + w;
    const float* xr = x + (size_t)row * K;
    __nv_bfloat16* xb = g_xb + (size_t)row * K;

    float4 v0 = *(const float4*)(xr + lane * 4);
    float4 v1 = *(const float4*)(xr + lane * 4 + 128);
    float4 v2 = *(const float4*)(xr + lane * 4 + 256);
    float4 v3 = *(const float4*)(xr + lane * 4 + 384);

    float s = 0.f;
    #define CVT_STORE(v, off) do {                                          \
        __nv_bfloat162 p0, p1;                                              \
        p0.x = __float2bfloat16((v).x); p0.y = __float2bfloat16((v).y);     \
        p1.x = __float2bfloat16((v).z); p1.y = __float2bfloat16((v).w);     \
        *(__nv_bfloat162*)(xb + (off))     = p0;                            \
        *(__nv_bfloat162*)(xb + (off) + 2) = p1;                            \
        float a = __bfloat162float(p0.x), b = __bfloat162float(p0.y);       \
        float c = __bfloat162float(p1.x), d = __bfloat162float(p1.y);       \
        s += a * a + b * b + c * c + d * d;                                 \
    } while (0)
    CVT_STORE(v0, lane * 4);
    CVT_STORE(v1, lane * 4 + 128);
    CVT_STORE(v2, lane * 4 + 256);
    CVT_STORE(v3, lane * 4 + 384);
    #undef CVT_STORE

    #pragma unroll
    for (int st = 16; st > 0; st >>= 1) s += __shfl_xor_sync(0xFFFFFFFFu, s, st);
    if (lane == 0) g_sqn[row] = s;
}

// ===========================================================================
// Kernel 1: bf16 HMMA Gram tile -> d (fp16, smem-staged coalesced stores),
// lower triangle. 3-stage cp.async pipeline, BK=64. NO extra tail code —
// this kernel is register-critical (proven by rounds 4 and 13).
// ===========================================================================
#define SSTRIDE 72
#define TILE_B  (128 * SSTRIDE * 2)
#define STAGE_B (2 * TILE_B)
#define SMEM_BYTES (3 * STAGE_B)
#define HSTRIDE 136

__global__ void __launch_bounds__(256, 2) gemm_kernel(int N, int K) {
    extern __shared__ char sm[];
    uint32_t smb = smem_u32(sm);

    int tid = threadIdx.x, lane = tid & 31, w = tid >> 5;
    int wy = w & 3, wx = w >> 2;

    int l = blockIdx.x;
    int bi = (int)((sqrtf(8.f * (float)l + 1.f) - 1.f) * 0.5f);
    while ((bi + 1) * (bi + 2) / 2 <= l) bi++;
    while (bi * (bi + 1) / 2 > l) bi--;
    int bj = l - bi * (bi + 1) / 2;

    const __nv_bfloat16* Ag = g_xb + (size_t)(bi * 128) * K;
    const __nv_bfloat16* Bg = g_xb + (size_t)(bj * 128) * K;

    float acc[2][8][4];
    #pragma unroll
    for (int mi = 0; mi < 2; mi++)
        #pragma unroll
        for (int ni = 0; ni < 8; ni++)
            #pragma unroll
            for (int q = 0; q < 4; q++) acc[mi][ni][q] = 0.f;

    uint32_t a_off = ((wy * 32 + (lane & 15)) * SSTRIDE + (lane >> 4) * 8) * 2;
    uint32_t b_off = ((wx * 64 + (lane & 7) + ((lane >> 4) << 3)) * SSTRIDE
                      + ((lane >> 3) & 1) * 8) * 2;

    int nch = K / 64;

    #define LOAD_STAGE(st, kt) do {                                          \
        uint32_t sa_ = smb + (st) * STAGE_B;                                 \
        _Pragma("unroll")                                                    \
        for (int p_ = 0; p_ < 4; p_++) {                                     \
            int idx_ = tid + p_ * 256;                                       \
            int row_ = idx_ >> 3, c8_ = idx_ & 7;                            \
            uint32_t so_ = sa_ + row_ * (SSTRIDE * 2) + c8_ * 16;            \
            CP_ASYNC16(so_,          Ag + (size_t)row_ * K + (kt) + c8_ * 8);\
            CP_ASYNC16(so_ + TILE_B, Bg + (size_t)row_ * K + (kt) + c8_ * 8);\
        }                                                                    \
        CP_COMMIT();                                                         \
    } while (0)

    LOAD_STAGE(0, 0);
    LOAD_STAGE(1, 64);

    int st_cur = 0, st_next = 2;
    for (int ch = 0; ch < nch; ch++) {
        if (ch == nch - 1) { CP_WAIT(0); } else { CP_WAIT(1); }
        __syncthreads();
        if (ch + 2 < nch) {
            LOAD_STAGE(st_next, (ch + 2) * 64);
        }

        uint32_t sa = smb + st_cur * STAGE_B;
        uint32_t sb = sa + TILE_B;
        #pragma unroll
        for (int kk = 0; kk < 4; kk++) {
            uint32_t a[2][4];
            #pragma unroll
            for (int mi = 0; mi < 2; mi++) {
                uint32_t ad = sa + a_off + (mi * 16 * SSTRIDE + kk * 16) * 2;
                LDSM_X4(a[mi][0], a[mi][1], a[mi][2], a[mi][3], ad);
            }
            uint32_t b[8][2];
            #pragma unroll
            for (int p = 0; p < 4; p++) {
                uint32_t bd = sb + b_off + (p * 16 * SSTRIDE + kk * 16) * 2;
                uint32_t r0, r1, r2, r3;
                LDSM_X4(r0, r1, r2, r3, bd);
                b[2 * p][0] = r0; b[2 * p][1] = r1;
                b[2 * p + 1][0] = r2; b[2 * p + 1][1] = r3;
            }
            #pragma unroll
            for (int mi = 0; mi < 2; mi++)
                #pragma unroll
                for (int ni = 0; ni < 8; ni++)
                    MMA_BF16(acc[mi][ni], a[mi], b[ni]);
        }

        st_cur  = (st_cur  + 1) % 3;
        st_next = (st_next + 1) % 3;
    }

    // ---- epilogue: d = sqrt(max(sq_i+sq_j-2G,0)); diag->0; fp16 via smem ----
    __syncthreads();
    __half* hsm = (__half*)sm;

    int gRow = lane >> 2, cPair = (lane & 3) * 2;
    float lsum = 0.f;
    #pragma unroll
    for (int mi = 0; mi < 2; mi++) {
        int r0  = wy * 32 + mi * 16 + gRow;
        int gi0 = bi * 128 + r0;
        int gi1 = gi0 + 8;
        float sq0 = g_sqn[gi0], sq1 = g_sqn[gi1];
        #pragma unroll
        for (int ni = 0; ni < 8; ni++) {
            int jloc = wx * 64 + ni * 8 + cPair;
            int gj = bj * 128 + jloc;
            float sqa = g_sqn[gj], sqb = g_sqn[gj + 1];
            float d00 = (gi0 == gj)     ? 0.f : sqrtf(fmaxf(sq0 + sqa - 2.f * acc[mi][ni][0], 0.f));
            float d01 = (gi0 == gj + 1) ? 0.f : sqrtf(fmaxf(sq0 + sqb - 2.f * acc[mi][ni][1], 0.f));
            float d10 = (gi1 == gj)     ? 0.f : sqrtf(fmaxf(sq1 + sqa - 2.f * acc[mi][ni][2], 0.f));
            float d11 = (gi1 == gj + 1) ? 0.f : sqrtf(fmaxf(sq1 + sqb - 2.f * acc[mi][ni][3], 0.f));
            lsum += d00 + d01 + d10 + d11;
            *(__half2*)&hsm[r0 * HSTRIDE + jloc]       = __floats2half2_rn(d00, d01);
            *(__half2*)&hsm[(r0 + 8) * HSTRIDE + jloc] = __floats2half2_rn(d10, d11);
        }
    }
    __syncthreads();

    // coalesced 16B stores: 128 rows x 128 halfs
    #pragma unroll
    for (int t = 0; t < 8; t++) {
        int idx = t * 256 + tid;
        int row = idx >> 4;
        int c8  = (idx & 15) << 3;
        uint4 v = *(uint4*)&hsm[row * HSTRIDE + c8];
        *(uint4*)(d_hbuf + (size_t)(bi * 128 + row) * N + bj * 128 + c8) = v;
    }

    #pragma unroll
    for (int s = 16; s > 0; s >>= 1) lsum += __shfl_xor_sync(0xFFFFFFFFu, lsum, s);
    __shared__ float wsum[8];
    if (lane == 0) wsum[w] = lsum;
    __syncthreads();
    if (tid == 0) {
        float s = 0.f;
        #pragma unroll
        for (int i = 0; i < 8; i++) s += wsum[i];
        g_partials[l] = s * ((bi == bj) ? 1.f : 2.f);
    }
}

// ===========================================================================
// Kernel 2: out[i,j] = sum_f 2^(d*coef_f). Per-CTA deterministic preamble
// computes bandwidth + coefficients (replaces reduce_kernel; round-9 proven).
// FMA/ALU-only exp2 (no MUFU, no conversions). 64x64 tiles -> 2080 CTAs.
// ===========================================================================
__global__ void __launch_bounds__(256) out_kernel(float* __restrict__ out,
                                                  const float* __restrict__ mult,
                                                  int N, int F, int nTiles) {
    int tid = threadIdx.x;
    __shared__ float red[256];
    __shared__ float scoef[8];
    __shared__ int   smode;
    __shared__ float smt[64][65];

    // ---- preamble: bandwidth + coefficients (identical in every CTA) ----
    {
        float s = 0.f;
        for (int i = tid; i < nTiles; i += 256) s += g_partials[i];
        red[tid] = s;
        __syncthreads();
        #pragma unroll
        for (int st = 128; st > 0; st >>= 1) {
            if (tid < st) red[tid] += red[tid + st];
            __syncthreads();
        }
        if (tid == 0) {
            float m[8];
            #pragma unroll
            for (int f = 0; f < 8; f++) m[f] = (f < F) ? mult[f] : 1.f;
            float bw = red[0] / ((float)N * (float)(N - 1));
            const float L2E = 1.4426950408889634f;
            bool geo = (F >= 1 && F <= 8);
            for (int f = 0; f + 1 < F && f < 7; f++)
                if (fabsf(m[f + 1] / m[f] - 2.f) > 1e-3f) geo = false;
            smode = geo ? 1 : 0;
            #pragma unroll
            for (int f = 0; f < 8; f++) scoef[f] = -L2E / (bw * m[f]);
        }
        __syncthreads();
    }

    int l = blockIdx.x;
    int bi = (int)((sqrtf(8.f * (float)l + 1.f) - 1.f) * 0.5f);
    while ((bi + 1) * (bi + 2) / 2 <= l) bi++;
    while (bi * (bi + 1) / 2 > l) bi--;
    int bj = l - bi * (bi + 1) / 2;

    int mode = smode;
    float cmax = scoef[F - 1];
    bool fast5 = (mode && F == 5);
    bool mirror = (bi != bj);

    int ibase = bi * 64;
    int jbase = bj * 64;

    // hoisted loads: both uint4 (2 x 8 halfs) in flight before any compute
    int il0 = tid >> 3,            jc0 = (tid & 7) << 3;
    int il1 = (256 + tid) >> 3,    jc1 = (tid & 7) << 3;
    size_t off0 = (size_t)(ibase + il0) * N + jbase + jc0;
    size_t off1 = (size_t)(ibase + il1) * N + jbase + jc1;
    uint4 raw0 = *(const uint4*)(d_hbuf + off0);
    uint4 raw1 = *(const uint4*)(d_hbuf + off1);

    #pragma unroll
    for (int t = 0; t < 2; t++) {
        uint4 raw = t ? raw1 : raw0;
        int il_ = t ? il1 : il0;
        int jc_ = t ? jc1 : jc0;
        size_t off = t ? off1 : off0;
        float2 f01 = __half22float2(*(__half2*)&raw.x);
        float2 f23 = __half22float2(*(__half2*)&raw.y);
        float2 f45 = __half22float2(*(__half2*)&raw.z);
        float2 f67 = __half22float2(*(__half2*)&raw.w);
        float dv[8] = {f01.x, f01.y, f23.x, f23.y, f45.x, f45.y, f67.x, f67.y};
        float sv[8];
        if (fast5) {
            #pragma unroll
            for (int e = 0; e < 8; e++) {
                float u = fexp2(dv[e] * cmax);
                float v2 = u * u, v4 = v2 * v2, v8 = v4 * v4, v16 = v8 * v8;
                sv[e] = ((u + v2) + (v4 + v8)) + v16;
            }
        } else if (mode) {
            #pragma unroll
            for (int e = 0; e < 8; e++) {
                float u = fexp2(dv[e] * cmax);
                float a = u, v = u;
                for (int k = 1; k < F; k++) { v *= v; a += v; }
                sv[e] = a;
            }
        } else {
            #pragma unroll
            for (int e = 0; e < 8; e++) sv[e] = 0.f;
            for (int f = 0; f < F; f++) {
                float cf = scoef[f];
                #pragma unroll
                for (int e = 0; e < 8; e++) sv[e] += fexp2(dv[e] * cf);
            }
        }
        float4 o0; o0.x = sv[0]; o0.y = sv[1]; o0.z = sv[2]; o0.w = sv[3];
        float4 o1; o1.x = sv[4]; o1.y = sv[5]; o1.z = sv[6]; o1.w = sv[7];
        *(float4*)(out + off)     = o0;
        *(float4*)(out + off + 4) = o1;
        if (mirror) {
            #pragma unroll
            for (int e = 0; e < 8; e++) smt[jc_ + e][il_] = sv[e];
        }
    }
    if (mirror) {
        __syncthreads();
        #pragma unroll
        for (int t = 0; t < 4; t++) {
            int idx4 = t * 256 + tid;
            int jr = idx4 >> 4;
            int i0 = (idx4 & 15) << 2;
            float4 v;
            v.x = smt[jr][i0 + 0];
            v.y = smt[jr][i0 + 1];
            v.z = smt[jr][i0 + 2];
            v.w = smt[jr][i0 + 3];
            *(float4*)(out + (size_t)(jbase + jr) * N + ibase + i0) = v;
        }
    }
}

// ===========================================================================
extern "C" void kernel_launch(void* const* d_in, const int* in_sizes, int n_in,
                              void* d_out, int out_size) {
    const float* x    = (const float*)d_in[0];
    const float* mult = (const float*)d_in[1];
    float* out        = (float*)d_out;

    int N = (int)(sqrt((double)out_size) + 0.5);
    int K = in_sizes[0] / N;
    int F = in_sizes[1];
    int T = N / 128;
    int LT = T * (T + 1) / 2;
    int T64 = N / 64;
    int LT64 = T64 * (T64 + 1) / 2;

    cudaFuncSetAttribute(gemm_kernel,
                         cudaFuncAttributeMaxDynamicSharedMemorySize, SMEM_BYTES);

    prep_kernel<<<N / 8, 256>>>(x, K);
    gemm_kernel<<<LT, 256, SMEM_BYTES>>>(N, K);
    out_kernel<<<LT64, 256>>>(out, mult, N, F, LT);
}

// round 16
// speedup vs baseline: 1.0331x; 1.0331x over previous
#include <cuda_runtime.h>
#include <cuda_bf16.h>
#include <cuda_fp16.h>
#include <math.h>
#include <stdint.h>

#define NMAX 4096
#define KMAX 512
#define LTMAX 1024   // >= 32*33/2 = 528 triangular tiles (gemm)

// ---- scratch (__device__ globals; allocation-free rule) ----
__device__ __half         d_hbuf[(size_t)NMAX * NMAX];  // distances, fp16
__device__ __nv_bfloat16  g_xb[(size_t)NMAX * KMAX];
__device__ float          g_sqn[NMAX];
__device__ float          g_partials[LTMAX];
__device__ float          g_coef[8];     // log2-scale: -log2(e)/(bw*mult_f)
__device__ int            g_mode;

// ===========================================================================
// helpers (generic PTX only: ldmatrix / mma.sync bf16 / cp.async)
// ===========================================================================
__device__ __forceinline__ uint32_t smem_u32(const void* p) {
    uint32_t a;
    asm("{ .reg .u64 t; cvta.to.shared.u64 t, %1; cvt.u32.u64 %0, t; }"
        : "=r"(a) : "l"(p));
    return a;
}

#define CP_ASYNC16(saddr, gptr) \
    asm volatile("cp.async.cg.shared.global [%0], [%1], 16;" \
                 :: "r"(saddr), "l"((const void*)(gptr)) : "memory")
#define CP_COMMIT()  asm volatile("cp.async.commit_group;" ::: "memory")
#define CP_WAIT(n)   asm volatile("cp.async.wait_group %0;" :: "n"(n) : "memory")

#define LDSM_X4(r0, r1, r2, r3, addr) \
    asm volatile("ldmatrix.sync.aligned.m8n8.x4.shared.b16 {%0,%1,%2,%3}, [%4];" \
                 : "=r"(r0), "=r"(r1), "=r"(r2), "=r"(r3) : "r"(addr))

#define MMA_BF16(c, a, b) \
    asm volatile("mma.sync.aligned.m16n8k16.row.col.f32.bf16.bf16.f32 " \
                 "{%0,%1,%2,%3}, {%4,%5,%6,%7}, {%8,%9}, {%0,%1,%2,%3};" \
                 : "+f"((c)[0]), "+f"((c)[1]), "+f"((c)[2]), "+f"((c)[3]) \
                 : "r"((a)[0]), "r"((a)[1]), "r"((a)[2]), "r"((a)[3]), \
                   "r"((b)[0]), "r"((b)[1]))

// FMA/ALU-only exp2: magic-number range reduction (no FRND, no F2I —
// conversion-class ops are quarter-rate). x <= 0 expected; clamped at -60.
__device__ __forceinline__ float fexp2(float x) {
    x = fmaxf(x, -60.f);
    const float MAGIC = 12582912.f;            // 2^23 * 1.5
    float y = __fadd_rn(x, MAGIC);             // RN -> nearest int in mantissa
    int   ni = __float_as_int(y) - 0x4B400000; // linear mantissa -> n
    float f = __fadd_rn(x, -__fadd_rn(y, -MAGIC));   // f = x - n, [-0.5, 0.5]
    float p = 1.33336e-3f;
    p = fmaf(p, f, 9.61813e-3f);
    p = fmaf(p, f, 5.550411e-2f);
    p = fmaf(p, f, 2.4022651e-1f);
    p = fmaf(p, f, 6.9314718e-1f);
    p = fmaf(p, f, 1.0f);
    return __int_as_float((ni + 127) << 23) * p;
}

// ===========================================================================
// Kernel 0: fused fp32 -> bf16 convert + row squared norms (warp per row,
// 4 unrolled float4 loads -> MLP=4/thread).
// ===========================================================================
__global__ void __launch_bounds__(256) prep_kernel(const float* __restrict__ x, int K) {
    int w    = threadIdx.x >> 5;
    int lane = threadIdx.x & 31;
    int row  = blockIdx.x * 8 + w;
    const float* xr = x + (size_t)row * K;
    __nv_bfloat16* xb = g_xb + (size_t)row * K;

    float4 v0 = *(const float4*)(xr + lane * 4);
    float4 v1 = *(const float4*)(xr + lane * 4 + 128);
    float4 v2 = *(const float4*)(xr + lane * 4 + 256);
    float4 v3 = *(const float4*)(xr + lane * 4 + 384);

    float s = 0.f;
    #define CVT_STORE(v, off) do {                                          \
        __nv_bfloat162 p0, p1;                                              \
        p0.x = __float2bfloat16((v).x); p0.y = __float2bfloat16((v).y);     \
        p1.x = __float2bfloat16((v).z); p1.y = __float2bfloat16((v).w);     \
        *(__nv_bfloat162*)(xb + (off))     = p0;                            \
        *(__nv_bfloat162*)(xb + (off) + 2) = p1;                            \
        float a = __bfloat162float(p0.x), b = __bfloat162float(p0.y);       \
        float c = __bfloat162float(p1.x), d = __bfloat162float(p1.y);       \
        s += a * a + b * b + c * c + d * d;                                 \
    } while (0)
    CVT_STORE(v0, lane * 4);
    CVT_STORE(v1, lane * 4 + 128);
    CVT_STORE(v2, lane * 4 + 256);
    CVT_STORE(v3, lane * 4 + 384);
    #undef CVT_STORE

    #pragma unroll
    for (int st = 16; st > 0; st >>= 1) s += __shfl_xor_sync(0xFFFFFFFFu, s, st);
    if (lane == 0) g_sqn[row] = s;
}

// ===========================================================================
// Kernel 1: bf16 HMMA Gram tile -> d (fp16, smem-staged coalesced stores),
// lower triangle. 3-stage cp.async pipeline, BK=64. NO extra tail code —
// this kernel is register-critical (proven by rounds 4 and 13).
// ===========================================================================
#define SSTRIDE 72
#define TILE_B  (128 * SSTRIDE * 2)
#define STAGE_B (2 * TILE_B)
#define SMEM_BYTES (3 * STAGE_B)
#define HSTRIDE 136

__global__ void __launch_bounds__(256, 2) gemm_kernel(int N, int K) {
    extern __shared__ char sm[];
    uint32_t smb = smem_u32(sm);

    int tid = threadIdx.x, lane = tid & 31, w = tid >> 5;
    int wy = w & 3, wx = w >> 2;

    int l = blockIdx.x;
    int bi = (int)((sqrtf(8.f * (float)l + 1.f) - 1.f) * 0.5f);
    while ((bi + 1) * (bi + 2) / 2 <= l) bi++;
    while (bi * (bi + 1) / 2 > l) bi--;
    int bj = l - bi * (bi + 1) / 2;

    const __nv_bfloat16* Ag = g_xb + (size_t)(bi * 128) * K;
    const __nv_bfloat16* Bg = g_xb + (size_t)(bj * 128) * K;

    float acc[2][8][4];
    #pragma unroll
    for (int mi = 0; mi < 2; mi++)
        #pragma unroll
        for (int ni = 0; ni < 8; ni++)
            #pragma unroll
            for (int q = 0; q < 4; q++) acc[mi][ni][q] = 0.f;

    uint32_t a_off = ((wy * 32 + (lane & 15)) * SSTRIDE + (lane >> 4) * 8) * 2;
    uint32_t b_off = ((wx * 64 + (lane & 7) + ((lane >> 4) << 3)) * SSTRIDE
                      + ((lane >> 3) & 1) * 8) * 2;

    int nch = K / 64;

    #define LOAD_STAGE(st, kt) do {                                          \
        uint32_t sa_ = smb + (st) * STAGE_B;                                 \
        _Pragma("unroll")                                                    \
        for (int p_ = 0; p_ < 4; p_++) {                                     \
            int idx_ = tid + p_ * 256;                                       \
            int row_ = idx_ >> 3, c8_ = idx_ & 7;                            \
            uint32_t so_ = sa_ + row_ * (SSTRIDE * 2) + c8_ * 16;            \
            CP_ASYNC16(so_,          Ag + (size_t)row_ * K + (kt) + c8_ * 8);\
            CP_ASYNC16(so_ + TILE_B, Bg + (size_t)row_ * K + (kt) + c8_ * 8);\
        }                                                                    \
        CP_COMMIT();                                                         \
    } while (0)

    LOAD_STAGE(0, 0);
    LOAD_STAGE(1, 64);

    int st_cur = 0, st_next = 2;
    for (int ch = 0; ch < nch; ch++) {
        if (ch == nch - 1) { CP_WAIT(0); } else { CP_WAIT(1); }
        __syncthreads();
        if (ch + 2 < nch) {
            LOAD_STAGE(st_next, (ch + 2) * 64);
        }

        uint32_t sa = smb + st_cur * STAGE_B;
        uint32_t sb = sa + TILE_B;
        #pragma unroll
        for (int kk = 0; kk < 4; kk++) {
            uint32_t a[2][4];
            #pragma unroll
            for (int mi = 0; mi < 2; mi++) {
                uint32_t ad = sa + a_off + (mi * 16 * SSTRIDE + kk * 16) * 2;
                LDSM_X4(a[mi][0], a[mi][1], a[mi][2], a[mi][3], ad);
            }
            uint32_t b[8][2];
            #pragma unroll
            for (int p = 0; p < 4; p++) {
                uint32_t bd = sb + b_off + (p * 16 * SSTRIDE + kk * 16) * 2;
                uint32_t r0, r1, r2, r3;
                LDSM_X4(r0, r1, r2, r3, bd);
                b[2 * p][0] = r0; b[2 * p][1] = r1;
                b[2 * p + 1][0] = r2; b[2 * p + 1][1] = r3;
            }
            #pragma unroll
            for (int mi = 0; mi < 2; mi++)
                #pragma unroll
                for (int ni = 0; ni < 8; ni++)
                    MMA_BF16(acc[mi][ni], a[mi], b[ni]);
        }

        st_cur  = (st_cur  + 1) % 3;
        st_next = (st_next + 1) % 3;
    }

    // ---- epilogue: d = sqrt(max(sq_i+sq_j-2G,0)); diag->0; fp16 via smem ----
    __syncthreads();
    __half* hsm = (__half*)sm;

    int gRow = lane >> 2, cPair = (lane & 3) * 2;
    float lsum = 0.f;
    #pragma unroll
    for (int mi = 0; mi < 2; mi++) {
        int r0  = wy * 32 + mi * 16 + gRow;
        int gi0 = bi * 128 + r0;
        int gi1 = gi0 + 8;
        float sq0 = g_sqn[gi0], sq1 = g_sqn[gi1];
        #pragma unroll
        for (int ni = 0; ni < 8; ni++) {
            int jloc = wx * 64 + ni * 8 + cPair;
            int gj = bj * 128 + jloc;
            float sqa = g_sqn[gj], sqb = g_sqn[gj + 1];
            float d00 = (gi0 == gj)     ? 0.f : sqrtf(fmaxf(sq0 + sqa - 2.f * acc[mi][ni][0], 0.f));
            float d01 = (gi0 == gj + 1) ? 0.f : sqrtf(fmaxf(sq0 + sqb - 2.f * acc[mi][ni][1], 0.f));
            float d10 = (gi1 == gj)     ? 0.f : sqrtf(fmaxf(sq1 + sqa - 2.f * acc[mi][ni][2], 0.f));
            float d11 = (gi1 == gj + 1) ? 0.f : sqrtf(fmaxf(sq1 + sqb - 2.f * acc[mi][ni][3], 0.f));
            lsum += d00 + d01 + d10 + d11;
            *(__half2*)&hsm[r0 * HSTRIDE + jloc]       = __floats2half2_rn(d00, d01);
            *(__half2*)&hsm[(r0 + 8) * HSTRIDE + jloc] = __floats2half2_rn(d10, d11);
        }
    }
    __syncthreads();

    // coalesced 16B stores: 128 rows x 128 halfs
    #pragma unroll
    for (int t = 0; t < 8; t++) {
        int idx = t * 256 + tid;
        int row = idx >> 4;
        int c8  = (idx & 15) << 3;
        uint4 v = *(uint4*)&hsm[row * HSTRIDE + c8];
        *(uint4*)(d_hbuf + (size_t)(bi * 128 + row) * N + bj * 128 + c8) = v;
    }

    #pragma unroll
    for (int s = 16; s > 0; s >>= 1) lsum += __shfl_xor_sync(0xFFFFFFFFu, lsum, s);
    __shared__ float wsum[8];
    if (lane == 0) wsum[w] = lsum;
    __syncthreads();
    if (tid == 0) {
        float s = 0.f;
        #pragma unroll
        for (int i = 0; i < 8; i++) s += wsum[i];
        g_partials[l] = s * ((bi == bj) ? 1.f : 2.f);
    }
}

// ===========================================================================
// Kernel 2: reduce partials -> bandwidth -> LOG2-scale exp coefs (+mode).
// ===========================================================================
__global__ void reduce_kernel(const float* __restrict__ mult, int N, int F, int nTiles) {
    __shared__ float red[512];
    __shared__ float smult[8];
    int tid = threadIdx.x;
    if (tid < 8 && tid < F) smult[tid] = mult[tid];
    float s = 0.f;
    for (int i = tid; i < nTiles; i += 512) s += g_partials[i];
    red[tid] = s;
    __syncthreads();
    #pragma unroll
    for (int st = 256; st > 0; st >>= 1) {
        if (tid < st) red[tid] += red[tid + st];
        __syncthreads();
    }
    if (tid == 0) {
        float bw = red[0] / ((float)N * (float)(N - 1));
        const float L2E = 1.4426950408889634f;
        bool geo = (F >= 1 && F <= 8);
        for (int f = 0; f + 1 < F && f < 7; f++)
            if (fabsf(smult[f + 1] / smult[f] - 2.f) > 1e-3f) geo = false;
        g_mode = geo ? 1 : 0;
        for (int f = 0; f < F && f < 8; f++)
            g_coef[f] = -L2E / (bw * smult[f]);
    }
}

// ===========================================================================
// Kernel 3: out[i,j] = sum_f 2^(d*coef_f). FMA/ALU-only exp2 (no MUFU, no
// conversion ops). 64x64 triangular tiles -> 2080 CTAs, dual hoisted loads.
// ===========================================================================
__global__ void __launch_bounds__(256) out_kernel(float* __restrict__ out, int N, int F) {
    int l = blockIdx.x;
    int bi = (int)((sqrtf(8.f * (float)l + 1.f) - 1.f) * 0.5f);
    while ((bi + 1) * (bi + 2) / 2 <= l) bi++;
    while (bi * (bi + 1) / 2 > l) bi--;
    int bj = l - bi * (bi + 1) / 2;

    __shared__ float smt[64][65];
    int tid = threadIdx.x;
    int mode = g_mode;
    float cmax = g_coef[F - 1];
    bool fast5 = (mode && F == 5);
    bool mirror = (bi != bj);

    int ibase = bi * 64;
    int jbase = bj * 64;

    // hoisted loads: both uint4 (2 x 8 halfs) in flight before any compute
    int il0 = tid >> 3,            jc0 = (tid & 7) << 3;
    int il1 = (256 + tid) >> 3,    jc1 = (tid & 7) << 3;
    size_t off0 = (size_t)(ibase + il0) * N + jbase + jc0;
    size_t off1 = (size_t)(ibase + il1) * N + jbase + jc1;
    uint4 raw0 = *(const uint4*)(d_hbuf + off0);
    uint4 raw1 = *(const uint4*)(d_hbuf + off1);

    #pragma unroll
    for (int t = 0; t < 2; t++) {
        uint4 raw = t ? raw1 : raw0;
        int il_ = t ? il1 : il0;
        int jc_ = t ? jc1 : jc0;
        size_t off = t ? off1 : off0;
        float2 f01 = __half22float2(*(__half2*)&raw.x);
        float2 f23 = __half22float2(*(__half2*)&raw.y);
        float2 f45 = __half22float2(*(__half2*)&raw.z);
        float2 f67 = __half22float2(*(__half2*)&raw.w);
        float dv[8] = {f01.x, f01.y, f23.x, f23.y, f45.x, f45.y, f67.x, f67.y};
        float sv[8];
        if (fast5) {
            #pragma unroll
            for (int e = 0; e < 8; e++) {
                float u = fexp2(dv[e] * cmax);
                float v2 = u * u, v4 = v2 * v2, v8 = v4 * v4, v16 = v8 * v8;
                sv[e] = ((u + v2) + (v4 + v8)) + v16;
            }
        } else if (mode) {
            #pragma unroll
            for (int e = 0; e < 8; e++) {
                float u = fexp2(dv[e] * cmax);
                float a = u, v = u;
                for (int k = 1; k < F; k++) { v *= v; a += v; }
                sv[e] = a;
            }
        } else {
            #pragma unroll
            for (int e = 0; e < 8; e++) sv[e] = 0.f;
            for (int f = 0; f < F; f++) {
                float cf = g_coef[f];
                #pragma unroll
                for (int e = 0; e < 8; e++) sv[e] += fexp2(dv[e] * cf);
            }
        }
        float4 o0; o0.x = sv[0]; o0.y = sv[1]; o0.z = sv[2]; o0.w = sv[3];
        float4 o1; o1.x = sv[4]; o1.y = sv[5]; o1.z = sv[6]; o1.w = sv[7];
        *(float4*)(out + off)     = o0;
        *(float4*)(out + off + 4) = o1;
        if (mirror) {
            #pragma unroll
            for (int e = 0; e < 8; e++) smt[jc_ + e][il_] = sv[e];
        }
    }
    if (mirror) {
        __syncthreads();
        #pragma unroll
        for (int t = 0; t < 4; t++) {
            int idx4 = t * 256 + tid;
            int jr = idx4 >> 4;
            int i0 = (idx4 & 15) << 2;
            float4 v;
            v.x = smt[jr][i0 + 0];
            v.y = smt[jr][i0 + 1];
            v.z = smt[jr][i0 + 2];
            v.w = smt[jr][i0 + 3];
            *(float4*)(out + (size_t)(jbase + jr) * N + ibase + i0) = v;
        }
    }
}

// ===========================================================================
extern "C" void kernel_launch(void* const* d_in, const int* in_sizes, int n_in,
                              void* d_out, int out_size) {
    const float* x    = (const float*)d_in[0];
    const float* mult = (const float*)d_in[1];
    float* out        = (float*)d_out;

    int N = (int)(sqrt((double)out_size) + 0.5);
    int K = in_sizes[0] / N;
    int F = in_sizes[1];
    int T = N / 128;
    int LT = T * (T + 1) / 2;
    int T64 = N / 64;
    int LT64 = T64 * (T64 + 1) / 2;

    cudaFuncSetAttribute(gemm_kernel,
                         cudaFuncAttributeMaxDynamicSharedMemorySize, SMEM_BYTES);

    prep_kernel<<<N / 8, 256>>>(x, K);
    gemm_kernel<<<LT, 256, SMEM_BYTES>>>(N, K);
    reduce_kernel<<<1, 512>>>(mult, N, F, LT);
    out_kernel<<<LT64, 256>>>(out, N, F);
}